// round 15
// baseline (speedup 1.0000x reference)
#include <cuda_runtime.h>
#include <cstdint>

#define N_LAYERS 512
#define BATCH    131072
#define TAB_N    (N_LAYERS + 1)      // padded for branch-free prefetch

__device__ __forceinline__ float inv1_of(int l, float pit) {
    const float DEL_Z = 0.9f / 512.0f;
    return 1.0f / (pit * (1.0f - DEL_Z * (float)l));
}

__global__ __launch_bounds__(128)
void metricnet_kernel(const float* __restrict__ Re_s,
                      const float* __restrict__ Im_s,
                      const float* __restrict__ Omega,
                      const float* __restrict__ PiT,
                      const float* __restrict__ B,
                      float* __restrict__ out)
{
    const float DEL_Z = 0.9f / 512.0f;
    const float MU2   = 1.0f;

    // Scalar per-layer tables (broadcast LDS):
    //   tabA = {P, Q2d, D2d, Ra2},  tabB = {Ua}
    // States: Xd = DEL_Z*(Re + inv1_l),  m = DEL_Z*omega*Im.
    //   Xd' = Xd*(P + 2m) + Q2d
    //   m'  = m*(m + P) + Ua + omega^2 * ( Ra2 - Xd'*(Xd' + D2d) )
    __shared__ float4 tabA[TAB_N];
    __shared__ float  tabB[TAB_N];

    const int tid = threadIdx.x;
    const float pit = PiT[0];

    for (int l = tid; l < TAB_N; l += blockDim.x) {
        int   lc    = (l < N_LAYERS) ? l : (N_LAYERS - 1);   // pad entry (content unused)
        float z     = DEL_Z * (float)lc;          // Z_INI = 0
        float omz   = 1.0f - z;
        float inv1  = 1.0f / (pit * omz);
        float inv1n = inv1_of(lc + 1, pit);
        float inv2  = inv1 / omz;
        float b1    = B[lc];
        float b2    = B[lc + 1];
        float g     = 1.0f - b2 / b1;
        float P     = 1.0f + g;
        float Q     = g * inv1 - DEL_Z * inv2;
        float R     = DEL_Z * (1.0f / (b1 * b1) - inv2 / pit);
        float U     = DEL_Z * z * z * MU2 / b1;
        float delta = inv1 - inv1n;
        float Q2    = Q - P * inv1 + inv1n;
        float Ra2   = DEL_Z * R + (DEL_Z * DEL_Z) * (inv1 * inv1 - delta * delta);
        float Ua    = -DEL_Z * U;
        float Q2d   = DEL_Z * Q2;
        float D2d   = 2.0f * DEL_Z * delta;
        tabA[l] = make_float4(P, Q2d, D2d, Ra2);
        tabB[l] = Ua;
    }
    __syncthreads();

    // One element per thread.
    const int i = blockIdx.x * blockDim.x + tid;   // [0, BATCH)

    const float inv1_0   = 1.0f / pit;             // inv1 at l=0
    const float inv1_end = inv1_of(N_LAYERS, pit); // inv1 at l=512

    const float om = Omega[i];
    const float dw = DEL_Z * om;
    float Xd = DEL_Z * (Re_s[i] + inv1_0);         // Xd = DEL_Z*(Re + inv1_0)
    float m  = dw * Im_s[i];                       // m = DEL_Z*omega*Im
    const float W2 = om * om;

    // software prefetch-by-1 through named registers
    float4 c  = tabA[0];     // P, Q2d, D2d, Ra2
    float  cu = tabB[0];     // Ua

    #pragma unroll 4
    for (int l = 0; l < N_LAYERS; ++l) {
        float4 n  = tabA[l + 1];
        float  nu = tabB[l + 1];

        const float P = c.x, Q2d = c.y, D2d = c.z, Ra2 = c.w, Ua = cu;

        float s   = m + P;                   // FADD
        float s2  = s + m;                   // FADD  (P + 2m)
        float Xn  = fmaf(Xd, s2, Q2d);       // FFMA  Xd' = Xd*(P+2m) + Q2d
        float acc = fmaf(m, s, Ua);          // FFMA  m*(m+P) + Ua
        float tv  = Xn + D2d;                // FADD  Xd' + D2d
        float u   = fmaf(-Xn, tv, Ra2);      // FFMA  Ra2 - Xd'*(Xd'+D2d)  (neg folds into FFMA)
        m  = fmaf(W2, u, acc);               // FFMA  m' = acc + omega^2*u
        Xd = Xn;

        c = n; cu = nu;
    }

    out[i]         = Xd / DEL_Z - inv1_end;  // Re_f
    out[BATCH + i] = m / dw;                 // Im_f
}

extern "C" void kernel_launch(void* const* d_in, const int* in_sizes, int n_in,
                              void* d_out, int out_size)
{
    const float* Re_s  = (const float*)d_in[0];
    const float* Im_s  = (const float*)d_in[1];
    const float* Omega = (const float*)d_in[2];
    const float* PiT   = (const float*)d_in[3];
    const float* B     = (const float*)d_in[4];
    float* out = (float*)d_out;

    const int threads = 128;
    const int blocks  = BATCH / threads;       // 1024 blocks
    metricnet_kernel<<<blocks, threads>>>(Re_s, Im_s, Omega, PiT, B, out);
}

// round 16
// speedup vs baseline: 1.3161x; 1.3161x over previous
#include <cuda_runtime.h>
#include <cstdint>

#define N_LAYERS 512
#define BATCH    131072
#define TAB_N    (N_LAYERS + 1)      // padded for branch-free prefetch

// Heterogeneous layout: 146 mixed CTAs (4 wide warps x 3 chains + 4 scalar warps)
// + 1 all-scalar remainder CTA.
#define MIXED_CTAS   146
#define WIDE_WARPS   (MIXED_CTAS * 4)          // 584
#define PAIR_STRIDE  (WIDE_WARPS * 32)         // 18688 pairs per chain slice
#define WIDE_ELEMS   (PAIR_STRIDE * 2 * 3)     // 112128 elements in wide region
#define SCALAR_BASE  WIDE_ELEMS                // 112128
#define SCALAR_MIXED (WIDE_WARPS * 32)         // 18688 scalar elems in mixed CTAs
#define LAST_BASE    (SCALAR_BASE + SCALAR_MIXED)  // 130816; last CTA covers 256

typedef unsigned long long u64;

__device__ __forceinline__ u64 pack2(float a, float b) {
    u64 r;
    asm("mov.b64 %0, {%1, %2};" : "=l"(r) : "f"(a), "f"(b));
    return r;
}
__device__ __forceinline__ u64 bcast2(float a) { return pack2(a, a); }
__device__ __forceinline__ void unpack2(u64 v, float& a, float& b) {
    asm("mov.b64 {%0, %1}, %2;" : "=f"(a), "=f"(b) : "l"(v));
}
__device__ __forceinline__ float lo2(u64 v) {   // low lane (register alias, free)
    float a, b; unpack2(v, a, b); return a;
}

#define FMA2(d, a, b, c) asm("fma.rn.f32x2 %0, %1, %2, %3;" : "=l"(d) : "l"(a), "l"(b), "l"(c))
#define MUL2(d, a, b)    asm("mul.rn.f32x2 %0, %1, %2;"     : "=l"(d) : "l"(a), "l"(b))
#define ADD2(d, a, b)    asm("add.rn.f32x2 %0, %1, %2;"     : "=l"(d) : "l"(a), "l"(b))

__device__ __forceinline__ float inv1_of(int l, float pit) {
    const float DEL_Z = 0.9f / 512.0f;
    return 1.0f / (pit * (1.0f - DEL_Z * (float)l));
}

__global__ __launch_bounds__(256, 1)
void metricnet_kernel(const float* __restrict__ Re_s,
                      const float* __restrict__ Im_s,
                      const float* __restrict__ Omega,
                      const float* __restrict__ PiT,
                      const float* __restrict__ B,
                      float* __restrict__ out)
{
    const float DEL_Z = 0.9f / 512.0f;
    const float MU2   = 1.0f;

    // Duplicated-lane u64 tables (wide warps use both lanes; scalar warps use low lane).
    // {P, Q2d} {ND2d(=-D2d), Ra2} {Ua}
    __shared__ ulonglong2 tabPQ[TAB_N];
    __shared__ ulonglong2 tabDR[TAB_N];
    __shared__ u64        tabU [TAB_N];

    const int tid  = threadIdx.x;
    const int wid  = tid >> 5;
    const int lane = tid & 31;
    const float pit = PiT[0];

    for (int l = tid; l < TAB_N; l += blockDim.x) {
        int   lc    = (l < N_LAYERS) ? l : (N_LAYERS - 1);   // pad entry (content unused)
        float z     = DEL_Z * (float)lc;          // Z_INI = 0
        float omz   = 1.0f - z;
        float inv1  = 1.0f / (pit * omz);
        float inv1n = inv1_of(lc + 1, pit);
        float inv2  = inv1 / omz;
        float b1    = B[lc];
        float b2    = B[lc + 1];
        float g     = 1.0f - b2 / b1;
        float P     = 1.0f + g;
        float Q     = g * inv1 - DEL_Z * inv2;
        float R     = DEL_Z * (1.0f / (b1 * b1) - inv2 / pit);
        float U     = DEL_Z * z * z * MU2 / b1;
        float delta = inv1 - inv1n;
        float Q2    = Q - P * inv1 + inv1n;
        float Ra2   = DEL_Z * R + (DEL_Z * DEL_Z) * (inv1 * inv1 - delta * delta);
        float Ua    = -DEL_Z * U;
        float Q2d   = DEL_Z * Q2;
        float ND2d  = -2.0f * DEL_Z * delta;
        tabPQ[l] = make_ulonglong2(bcast2(P),    bcast2(Q2d));
        tabDR[l] = make_ulonglong2(bcast2(ND2d), bcast2(Ra2));
        tabU[l]  = bcast2(Ua);
    }
    __syncthreads();

    const float inv1_0   = 1.0f / pit;                 // inv1 at l=0
    const float inv1_end = inv1_of(N_LAYERS, pit);     // inv1 at l=512

    const bool mixed  = (blockIdx.x < MIXED_CTAS);
    const bool isWide = mixed && (wid < 4);

    if (isWide) {
        // ---------------- wide path: 3 chains of element-pairs ----------------
        const int p0 = (blockIdx.x * 4 + wid) * 32 + lane;   // pair index, chain 0

        u64 Xd[3], Mm[3], W2[3];
        float dwx[3], dwy[3];

        #pragma unroll
        for (int k = 0; k < 3; ++k) {
            const int idx = p0 + k * PAIR_STRIDE;
            const float2 re = ((const float2*)Re_s)[idx];
            const float2 im = ((const float2*)Im_s)[idx];
            const float2 om = ((const float2*)Omega)[idx];
            dwx[k] = DEL_Z * om.x;
            dwy[k] = DEL_Z * om.y;
            Xd[k] = pack2(DEL_Z * (re.x + inv1_0), DEL_Z * (re.y + inv1_0));
            Mm[k] = pack2(dwx[k] * im.x, dwy[k] * im.y);
            W2[k] = pack2(om.x * om.x, om.y * om.y);
        }

        const u64 NONE = bcast2(-1.0f);

        ulonglong2 c0 = tabPQ[0];
        ulonglong2 c1 = tabDR[0];
        u64        cu = tabU[0];

        #pragma unroll 4
        for (int l = 0; l < N_LAYERS; ++l) {
            ulonglong2 n0 = tabPQ[l + 1];
            ulonglong2 n1 = tabDR[l + 1];
            u64        nu = tabU[l + 1];

            u64 P = c0.x, Q2d = c0.y, ND2d = c1.x, Ra2 = c1.y, Ua = cu;

            #pragma unroll
            for (int k = 0; k < 3; ++k) {
                u64 s, s2, Xn, acc, tv, u, Mn;
                ADD2(s,  Mm[k], P);
                ADD2(s2, s,  Mm[k]);            // P + 2m
                FMA2(Xn, Xd[k], s2, Q2d);       // Xd' = Xd*(P+2m) + Q2d
                FMA2(acc, Mm[k], s, Ua);        // m*(m+P) + Ua
                FMA2(tv, NONE, Xn, ND2d);       // -Xd' - D2d
                FMA2(u,  Xn, tv, Ra2);          // Ra2 - Xd'*(Xd'+D2d)
                FMA2(Mn, W2[k], u, acc);        // m' = acc + omega^2 * u
                Xd[k] = Xn;
                Mm[k] = Mn;
            }
            c0 = n0; c1 = n1; cu = nu;
        }

        #pragma unroll
        for (int k = 0; k < 3; ++k) {
            const int idx = p0 + k * PAIR_STRIDE;
            float2 xo, mo, reo, imo;
            unpack2(Xd[k], xo.x, xo.y);
            unpack2(Mm[k], mo.x, mo.y);
            reo.x = xo.x / DEL_Z - inv1_end;
            reo.y = xo.y / DEL_Z - inv1_end;
            imo.x = mo.x / dwx[k];
            imo.y = mo.y / dwy[k];
            ((float2*)out)[idx]           = reo;
            ((float2*)(out + BATCH))[idx] = imo;
        }
    } else {
        // ---------------- scalar path: 1 element per thread ----------------
        int e;
        if (mixed) e = SCALAR_BASE + (blockIdx.x * 4 + (wid - 4)) * 32 + lane;
        else       e = LAST_BASE + wid * 32 + lane;   // remainder CTA (256 elems)

        const float om = Omega[e];
        const float dw = DEL_Z * om;
        float Xd = DEL_Z * (Re_s[e] + inv1_0);
        float m  = dw * Im_s[e];
        const float W2 = om * om;

        ulonglong2 c0 = tabPQ[0];
        ulonglong2 c1 = tabDR[0];
        u64        cu = tabU[0];

        #pragma unroll 4
        for (int l = 0; l < N_LAYERS; ++l) {
            ulonglong2 n0 = tabPQ[l + 1];
            ulonglong2 n1 = tabDR[l + 1];
            u64        nu = tabU[l + 1];

            const float P    = lo2(c0.x);
            const float Q2d  = lo2(c0.y);
            const float nd2d = lo2(c1.x);      // = -D2d
            const float Ra2  = lo2(c1.y);
            const float Ua   = lo2(cu);

            float s   = m + P;
            float s2  = s + m;                   // P + 2m
            float Xn  = fmaf(Xd, s2, Q2d);
            float acc = fmaf(m, s, Ua);
            float tv  = Xn - nd2d;               // Xd' + D2d
            float u   = fmaf(-Xn, tv, Ra2);
            m  = fmaf(W2, u, acc);
            Xd = Xn;

            c0 = n0; c1 = n1; cu = nu;
        }

        out[e]         = Xd / DEL_Z - inv1_end;
        out[BATCH + e] = m / dw;
    }
}

extern "C" void kernel_launch(void* const* d_in, const int* in_sizes, int n_in,
                              void* d_out, int out_size)
{
    const float* Re_s  = (const float*)d_in[0];
    const float* Im_s  = (const float*)d_in[1];
    const float* Omega = (const float*)d_in[2];
    const float* PiT   = (const float*)d_in[3];
    const float* B     = (const float*)d_in[4];
    float* out = (float*)d_out;

    const int threads = 256;                   // 8 warps: 4 wide + 4 scalar
    const int blocks  = MIXED_CTAS + 1;        // 147 CTAs (last = remainder, all-scalar)
    metricnet_kernel<<<blocks, threads>>>(Re_s, Im_s, Omega, PiT, B, out);
}